// round 8
// baseline (speedup 1.0000x reference)
#include <cuda_runtime.h>
#include <cuda_bf16.h>
#include <math_constants.h>

#define EPSF 1e-7f
#define NMAX 4096
#define NT_MAX 128   // NMAX / 32

// Per-box precomputed features (device scratch; no allocations).
__device__ float4 g_A[NMAX];  // x1, y1, x2, y2
__device__ float4 g_B[NMAX];  // area, x1+x2, y1+y2, atan(w/(h+eps))
__device__ float  g_C[NMAX];  // conf
// Partial sums: for each row, one 6-vector per partner tile. Written exactly
// once per slot (deterministic), reduced in a fixed order by tgam_reduce.
__device__ float  g_part[NMAX][NT_MAX][6];

__global__ void tgam_prep(const float* __restrict__ x, int n) {
    int i = blockIdx.x * blockDim.x + threadIdx.x;
    if (i >= n) return;
    float conf = x[i * 5 + 0];
    float x1 = x[i * 5 + 1];
    float y1 = x[i * 5 + 2];
    float x2 = x[i * 5 + 3];
    float y2 = x[i * 5 + 4];
    float w = x2 - x1;
    float h = y2 - y1;
    g_A[i] = make_float4(x1, y1, x2, y2);
    g_B[i] = make_float4(w * h, x1 + x2, y1 + y2, atanf(__fdividef(w, h + EPSF)));
    g_C[i] = conf;
}

__device__ __forceinline__ float safe_sigmoid(float xp) {
    float r = __fdividef(1.0f, 1.0f + __expf(-xp));
    return isfinite(r) ? r : 0.5f;
}

// Shared per-pair CIoU->exp score. Identical math to the round-6 passing
// kernel (incl. the diagonal-safe iou clamp), with log2(e) folded into cil2.
__device__ __forceinline__ float pair_score(
    const float4 Ai, const float4 Bi, const float biE, const float cil2,
    const float4 Aj, const float4 Bj, const float cj)
{
    const float K = 4.0f / (CUDART_PI_F * CUDART_PI_F);

    float iw = fminf(Ai.z, Aj.z) - fmaxf(Ai.x, Aj.x);
    float ih = fminf(Ai.w, Aj.w) - fmaxf(Ai.y, Aj.y);
    iw = fmaxf(iw, 0.0f);
    ih = fmaxf(ih, 0.0f);
    const float inter = iw * ih;

    const float uni = (Bj.x + biE) - inter;
    const float iou = fminf(__fdividef(inter, uni), 1.0f);  // NaN-proof clamp

    const float cw = fmaxf(Ai.z, Aj.z) - fminf(Ai.x, Aj.x);
    const float ch = fmaxf(Ai.w, Aj.w) - fminf(Ai.y, Aj.y);
    const float c2 = cw * cw + ch * ch + EPSF;

    const float dx = Bj.y - Bi.y;
    const float dy = Bj.z - Bi.z;
    const float rho2 = 0.25f * (dx * dx + dy * dy);

    const float da = Bj.w - Bi.w;
    const float v  = K * da * da;
    const float alpha = __fdividef(v, v - iou + (1.0f + EPSF));

    const float ciou = iou - (__fdividef(rho2, c2) + v * alpha);

    // p = exp(ciou * ci * cj) = ex2(ciou * (ci*log2e) * cj)
    const float s2 = ciou * (cil2 * cj);
    float p;
    asm("ex2.approx.f32 %0, %1;" : "=f"(p) : "f"(s2));
    return p;
}

// One warp per unordered tile pair (a <= b), tiles of 32 rows.
// Lane l owns row a*32+l; for a<b it also owns row b*32+l via the mirror:
// p is symmetric, so the score lane (l-k) computed at step k is exactly
// p_{a32+(l-k), b32+l} -> shuffle it and accumulate with f(a32+(l-k)).
__global__ __launch_bounds__(256) void tgam_pairs(int n, int NT) {
    const int w    = blockIdx.x * 8 + (threadIdx.x >> 5);
    const int lane = threadIdx.x & 31;
    const int total = (NT * (NT + 1)) >> 1;
    if (w >= total) return;

    // Decode w -> (a, b), a <= b.  base(a) = a*(2*NT - a + 1)/2.
    float fs = sqrtf((float)((2 * NT + 1) * (2 * NT + 1) - 8 * w));
    int a = (int)(((float)(2 * NT + 1) - fs) * 0.5f);
    if (a < 0) a = 0;
    if (a > NT - 1) a = NT - 1;
    while (a > 0 && (a * (2 * NT - a + 1)) / 2 > w) a--;
    while (((a + 1) * (2 * NT - a)) / 2 <= w) a++;
    const int base = (a * (2 * NT - a + 1)) / 2;
    const int b = a + (w - base);
    const bool diag = (a == b);

    const int rA = a * 32 + lane;
    const float4 Ai = g_A[rA];
    const float4 Bi = g_B[rA];
    const float  ci = g_C[rA];
    const float  cil2 = ci * 1.44269504f;
    const float  biE  = Bi.x + EPSF;

    const int jbase = b * 32;
    const int ibase = a * 32;

    float lA = 0.f, a0A = 0.f, a1A = 0.f, a2A = 0.f, a3A = 0.f, a4A = 0.f;
    float lB = 0.f, a0B = 0.f, a1B = 0.f, a2B = 0.f, a3B = 0.f, a4B = 0.f;

#pragma unroll 2
    for (int k = 0; k < 32; k++) {
        const int jl = (lane + k) & 31;
        const int j  = jbase + jl;
        const float4 Aj = g_A[j];
        const float4 Bj = g_B[j];
        const float  cj = g_C[j];

        const float p = pair_score(Ai, Bi, biE, cil2, Aj, Bj, cj);

        lA  += p;
        a0A += p * cj;
        a1A += p * Aj.x;
        a2A += p * Aj.y;
        a3A += p * Aj.z;
        a4A += p * Aj.w;

        // Mirror (uniform branch across warp; shfl is warp-collective-safe).
        const int src = (lane - k) & 31;
        const float ps = __shfl_sync(0xFFFFFFFFu, p, src);
        if (!diag) {
            const int ip = ibase + src;
            const float4 Ap = g_A[ip];
            const float  cp = g_C[ip];
            lB  += ps;
            a0B += ps * cp;
            a1B += ps * Ap.x;
            a2B += ps * Ap.y;
            a3B += ps * Ap.z;
            a4B += ps * Ap.w;
        }
    }

    // Write partials (each [row][slot] written exactly once).
    {
        float2* pr = (float2*)&g_part[rA][b][0];
        pr[0] = make_float2(lA, a0A);
        pr[1] = make_float2(a1A, a2A);
        pr[2] = make_float2(a3A, a4A);
    }
    if (!diag) {
        const int rB = jbase + lane;
        float2* pr = (float2*)&g_part[rB][a][0];
        pr[0] = make_float2(lB, a0B);
        pr[1] = make_float2(a1B, a2B);
        pr[2] = make_float2(a3B, a4B);
    }
}

// Block per row: sum NT partial 6-vectors (fixed order -> deterministic),
// then apply gamma, softmax-normalize, sigmoid.
__global__ __launch_bounds__(128) void tgam_reduce(
    const float* __restrict__ gamma_p, float* __restrict__ out, int NT)
{
    const int r = blockIdx.x;
    const int t = threadIdx.x;

    float l = 0.f, b0 = 0.f, b1 = 0.f, b2 = 0.f, b3 = 0.f, b4 = 0.f;
    if (t < NT) {
        const float2* pr = (const float2*)&g_part[r][t][0];
        float2 v0 = pr[0], v1 = pr[1], v2 = pr[2];
        l = v0.x; b0 = v0.y; b1 = v1.x; b2 = v1.y; b3 = v2.x; b4 = v2.y;
    }

#pragma unroll
    for (int o = 16; o > 0; o >>= 1) {
        l  += __shfl_xor_sync(0xFFFFFFFFu, l,  o);
        b0 += __shfl_xor_sync(0xFFFFFFFFu, b0, o);
        b1 += __shfl_xor_sync(0xFFFFFFFFu, b1, o);
        b2 += __shfl_xor_sync(0xFFFFFFFFu, b2, o);
        b3 += __shfl_xor_sync(0xFFFFFFFFu, b3, o);
        b4 += __shfl_xor_sync(0xFFFFFFFFu, b4, o);
    }

    __shared__ float red[4][6];
    const int warp = t >> 5;
    const int lane = t & 31;
    if (lane == 0) {
        red[warp][0] = l;  red[warp][1] = b0; red[warp][2] = b1;
        red[warp][3] = b2; red[warp][4] = b3; red[warp][5] = b4;
    }
    __syncthreads();

    if (t == 0) {
        float L = 0.f, A0 = 0.f, A1 = 0.f, A2 = 0.f, A3 = 0.f, A4 = 0.f;
#pragma unroll
        for (int wv = 0; wv < 4; wv++) {
            L  += red[wv][0]; A0 += red[wv][1]; A1 += red[wv][2];
            A2 += red[wv][3]; A3 += red[wv][4]; A4 += red[wv][5];
        }
        const float inv = __fdividef(1.0f, L);

        float g = gamma_p[0];
        if (!isfinite(g)) g = 0.0f;

        const float4 Ai = g_A[r];
        const float  ci = g_C[r];

        out[r * 5 + 0] = safe_sigmoid(ci   * g + A0 * inv);
        out[r * 5 + 1] = safe_sigmoid(Ai.x * g + A1 * inv);
        out[r * 5 + 2] = safe_sigmoid(Ai.y * g + A2 * inv);
        out[r * 5 + 3] = safe_sigmoid(Ai.z * g + A3 * inv);
        out[r * 5 + 4] = safe_sigmoid(Ai.w * g + A4 * inv);
    }
}

// ---------- Fallback (round-6 passing kernel): row per CTA ----------
__global__ __launch_bounds__(256) void tgam_attn_fb(
    const float* __restrict__ gamma_p, float* __restrict__ out, int n)
{
    const int i = blockIdx.x;
    const int tid = threadIdx.x;
    const float4 Ai = g_A[i];
    const float4 Bi = g_B[i];
    const float  ci = g_C[i];
    const float  cil2 = ci * 1.44269504f;
    const float  biE  = Bi.x + EPSF;

    float l = 0.f, a0 = 0.f, a1 = 0.f, a2 = 0.f, a3 = 0.f, a4 = 0.f;
#pragma unroll 4
    for (int j = tid; j < n; j += 256) {
        const float4 Aj = g_A[j];
        const float4 Bj = g_B[j];
        const float  cj = g_C[j];
        const float p = pair_score(Ai, Bi, biE, cil2, Aj, Bj, cj);
        l += p; a0 += p * cj;
        a1 += p * Aj.x; a2 += p * Aj.y; a3 += p * Aj.z; a4 += p * Aj.w;
    }
#pragma unroll
    for (int o = 16; o > 0; o >>= 1) {
        l  += __shfl_xor_sync(0xFFFFFFFFu, l,  o);
        a0 += __shfl_xor_sync(0xFFFFFFFFu, a0, o);
        a1 += __shfl_xor_sync(0xFFFFFFFFu, a1, o);
        a2 += __shfl_xor_sync(0xFFFFFFFFu, a2, o);
        a3 += __shfl_xor_sync(0xFFFFFFFFu, a3, o);
        a4 += __shfl_xor_sync(0xFFFFFFFFu, a4, o);
    }
    __shared__ float red[8][6];
    const int warp = tid >> 5, lane = tid & 31;
    if (lane == 0) {
        red[warp][0] = l;  red[warp][1] = a0; red[warp][2] = a1;
        red[warp][3] = a2; red[warp][4] = a3; red[warp][5] = a4;
    }
    __syncthreads();
    if (tid == 0) {
        float L = 0.f, A0 = 0.f, A1 = 0.f, A2 = 0.f, A3 = 0.f, A4 = 0.f;
#pragma unroll
        for (int wv = 0; wv < 8; wv++) {
            L += red[wv][0]; A0 += red[wv][1]; A1 += red[wv][2];
            A2 += red[wv][3]; A3 += red[wv][4]; A4 += red[wv][5];
        }
        const float inv = __fdividef(1.0f, L);
        float g = gamma_p[0];
        if (!isfinite(g)) g = 0.0f;
        out[i * 5 + 0] = safe_sigmoid(ci   * g + A0 * inv);
        out[i * 5 + 1] = safe_sigmoid(Ai.x * g + A1 * inv);
        out[i * 5 + 2] = safe_sigmoid(Ai.y * g + A2 * inv);
        out[i * 5 + 3] = safe_sigmoid(Ai.z * g + A3 * inv);
        out[i * 5 + 4] = safe_sigmoid(Ai.w * g + A4 * inv);
    }
}

extern "C" void kernel_launch(void* const* d_in, const int* in_sizes, int n_in,
                              void* d_out, int out_size) {
    // x = the big tensor, gamma = the 1-element one (ordering-proof).
    int xi = 0, gi = (n_in > 1) ? 1 : 0;
    if (n_in > 1 && in_sizes[1] > in_sizes[0]) { xi = 1; gi = 0; }

    const float* x     = (const float*)d_in[xi];
    const float* gamma = (const float*)d_in[gi];
    float* out         = (float*)d_out;

    const int denom = (n_in > 1 && in_sizes[gi] == 4) ? 20 : 5;
    int n = in_sizes[xi] / denom;
    if (out_size > 0) {
        int n_out = out_size / denom;
        if (n_out > 0 && n_out < n) n = n_out;
    }
    if (n > NMAX) n = NMAX;
    if (n <= 0) n = 1;

    tgam_prep<<<(n + 255) / 256, 256>>>(x, n);

    if ((n & 31) == 0 && (n >> 5) <= NT_MAX) {
        const int NT = n >> 5;
        const int total = (NT * (NT + 1)) >> 1;      // warp jobs
        const int ctas  = (total + 7) / 8;
        tgam_pairs<<<ctas, 256>>>(n, NT);
        tgam_reduce<<<n, 128>>>(gamma, out, NT);
    } else {
        tgam_attn_fb<<<n, 256>>>(gamma, out, n);
    }
}

// round 9
// speedup vs baseline: 1.1705x; 1.1705x over previous
#include <cuda_runtime.h>
#include <cuda_bf16.h>
#include <math_constants.h>

#define EPSF 1e-7f
#define NMAX 8192
#define L2E  1.44269504f

// Interleaved per-box features: 3 float4 per box (single base pointer in loop).
//  [3i+0] = x1, y1, x2, y2
//  [3i+1] = area, 0.5*(x1+x2), 0.5*(y1+y2), (2/pi)*atan(w/(h+eps))
//  [3i+2] = conf, w, h, (spare)
__device__ float4 g_F[NMAX * 3];

__global__ void tgam_prep(const float* __restrict__ x, int n) {
    int i = blockIdx.x * blockDim.x + threadIdx.x;
    if (i >= n) return;
    float conf = x[i * 5 + 0];
    float x1 = x[i * 5 + 1];
    float y1 = x[i * 5 + 2];
    float x2 = x[i * 5 + 3];
    float y2 = x[i * 5 + 4];
    float w = x2 - x1;
    float h = y2 - y1;
    const float TWO_OVER_PI = 0.63661977236758134f;
    g_F[3 * i + 0] = make_float4(x1, y1, x2, y2);
    g_F[3 * i + 1] = make_float4(w * h, 0.5f * (x1 + x2), 0.5f * (y1 + y2),
                                 TWO_OVER_PI * atanf(__fdividef(w, h + EPSF)));
    g_F[3 * i + 2] = make_float4(conf, w, h, 0.0f);
}

__device__ __forceinline__ float safe_sigmoid(float xp) {
    float r = __fdividef(1.0f, 1.0f + __expf(-xp));
    return isfinite(r) ? r : 0.5f;
}

struct RowFeat {
    float x1, y1, x2, y2;   // box
    float biE;              // area + EPSF
    float sxh, syh;         // half center sums
    float atK;              // (2/pi)*atan
    float w, h;             // width, height
    float cil2;             // conf * log2(e)
    float conf;
};

__device__ __forceinline__ RowFeat load_row(int i) {
    RowFeat r;
    float4 A = g_F[3 * i + 0];
    float4 B = g_F[3 * i + 1];
    float4 C = g_F[3 * i + 2];
    r.x1 = A.x; r.y1 = A.y; r.x2 = A.z; r.y2 = A.w;
    r.biE = B.x + EPSF;
    r.sxh = B.y; r.syh = B.z; r.atK = B.w;
    r.conf = C.x; r.w = C.y; r.h = C.z;
    r.cil2 = C.x * L2E;
    return r;
}

// Per-pair score. Exact CIoU math with per-box constants prefolded:
//  - cw = (wi+wj) - iw_raw   (min+max identity, replaces 2 FMNMX + sub)
//  - v  = da^2 with da in (2/pi)*atan units (K prefolded)
//  - rho2 = dx^2+dy^2 with half center sums (0.25 prefolded)
//  - v*alpha = v^2/den (one fused divide)
//  - p = ex2(ciou * cil2 * cj) (log2e prefolded)
__device__ __forceinline__ float score(
    const RowFeat& Ri, const float4 Fa, const float4 Fb, const float4 Fc,
    const float one_eps, const float epsr)
{
    float iwr = fminf(Ri.x2, Fa.z) - fmaxf(Ri.x1, Fa.x);
    float ihr = fminf(Ri.y2, Fa.w) - fmaxf(Ri.y1, Fa.y);
    float iw = fmaxf(iwr, 0.0f);
    float ih = fmaxf(ihr, 0.0f);
    float inter = iw * ih;

    float uni = (Ri.biE + Fb.x) - inter;
    float iou = fminf(__fdividef(inter, uni), 1.0f);  // clamp: NaN-proof + more accurate

    float cw = (Ri.w + Fc.y) - iwr;
    float ch = (Ri.h + Fc.z) - ihr;
    float c2 = fmaf(cw, cw, fmaf(ch, ch, epsr));

    float dx = Fb.y - Ri.sxh;
    float dy = Fb.z - Ri.syh;
    float rho2 = fmaf(dx, dx, dy * dy);
    float t2 = __fdividef(rho2, c2);

    float da = Fb.w - Ri.atK;
    float v  = da * da;
    float den = (v + one_eps) - iou;       // >= EPSF since iou <= 1
    float t3 = __fdividef(v * v, den);     // = v * alpha

    float ciou = (iou - t2) - t3;

    float s2 = ciou * (Ri.cil2 * Fc.x);
    float p;
    asm("ex2.approx.f32 %0, %1;" : "=f"(p) : "f"(s2));
    return p;
}

// Two rows per CTA: j-features (3 x LDG.128) amortize over 2 pairs.
__global__ __launch_bounds__(256) void tgam_attn2(
    const float* __restrict__ gamma_p, float* __restrict__ out, int n)
{
    const int i0 = blockIdx.x * 2;
    const int i1 = (i0 + 1 < n) ? (i0 + 1) : i0;
    const int tid = threadIdx.x;

    const RowFeat R0 = load_row(i0);
    const RowFeat R1 = load_row(i1);
    const float one_eps = 1.0f + EPSF;
    const float epsr = EPSF;

    float l0 = 0.f, b00 = 0.f, b01 = 0.f, b02 = 0.f, b03 = 0.f, b04 = 0.f;
    float l1 = 0.f, b10 = 0.f, b11 = 0.f, b12 = 0.f, b13 = 0.f, b14 = 0.f;

#pragma unroll 4
    for (int j = tid; j < n; j += 256) {
        const float4 Fa = g_F[3 * j + 0];
        const float4 Fb = g_F[3 * j + 1];
        const float4 Fc = g_F[3 * j + 2];

        const float p0 = score(R0, Fa, Fb, Fc, one_eps, epsr);
        l0  += p0;
        b00 += p0 * Fc.x;
        b01 += p0 * Fa.x;
        b02 += p0 * Fa.y;
        b03 += p0 * Fa.z;
        b04 += p0 * Fa.w;

        const float p1 = score(R1, Fa, Fb, Fc, one_eps, epsr);
        l1  += p1;
        b10 += p1 * Fc.x;
        b11 += p1 * Fa.x;
        b12 += p1 * Fa.y;
        b13 += p1 * Fa.z;
        b14 += p1 * Fa.w;
    }

    // ---- block reduction of 12 values ----
#pragma unroll
    for (int o = 16; o > 0; o >>= 1) {
        l0  += __shfl_xor_sync(0xFFFFFFFFu, l0,  o);
        b00 += __shfl_xor_sync(0xFFFFFFFFu, b00, o);
        b01 += __shfl_xor_sync(0xFFFFFFFFu, b01, o);
        b02 += __shfl_xor_sync(0xFFFFFFFFu, b02, o);
        b03 += __shfl_xor_sync(0xFFFFFFFFu, b03, o);
        b04 += __shfl_xor_sync(0xFFFFFFFFu, b04, o);
        l1  += __shfl_xor_sync(0xFFFFFFFFu, l1,  o);
        b10 += __shfl_xor_sync(0xFFFFFFFFu, b10, o);
        b11 += __shfl_xor_sync(0xFFFFFFFFu, b11, o);
        b12 += __shfl_xor_sync(0xFFFFFFFFu, b12, o);
        b13 += __shfl_xor_sync(0xFFFFFFFFu, b13, o);
        b14 += __shfl_xor_sync(0xFFFFFFFFu, b14, o);
    }

    __shared__ float red[8][12];
    const int warp = tid >> 5;
    const int lane = tid & 31;
    if (lane == 0) {
        red[warp][0]  = l0;  red[warp][1]  = b00; red[warp][2]  = b01;
        red[warp][3]  = b02; red[warp][4]  = b03; red[warp][5]  = b04;
        red[warp][6]  = l1;  red[warp][7]  = b10; red[warp][8]  = b11;
        red[warp][9]  = b12; red[warp][10] = b13; red[warp][11] = b14;
    }
    __syncthreads();

    if (tid == 0) {
        float S[12];
#pragma unroll
        for (int v = 0; v < 12; v++) {
            float s = 0.f;
#pragma unroll
            for (int w = 0; w < 8; w++) s += red[w][v];
            S[v] = s;
        }
        float g = gamma_p[0];
        if (!isfinite(g)) g = 0.0f;

        {
            const float inv = __fdividef(1.0f, S[0]);
            out[i0 * 5 + 0] = safe_sigmoid(R0.conf * g + S[1] * inv);
            out[i0 * 5 + 1] = safe_sigmoid(R0.x1   * g + S[2] * inv);
            out[i0 * 5 + 2] = safe_sigmoid(R0.y1   * g + S[3] * inv);
            out[i0 * 5 + 3] = safe_sigmoid(R0.x2   * g + S[4] * inv);
            out[i0 * 5 + 4] = safe_sigmoid(R0.y2   * g + S[5] * inv);
        }
        if (i1 != i0) {
            const float inv = __fdividef(1.0f, S[6]);
            out[i1 * 5 + 0] = safe_sigmoid(R1.conf * g + S[7]  * inv);
            out[i1 * 5 + 1] = safe_sigmoid(R1.x1   * g + S[8]  * inv);
            out[i1 * 5 + 2] = safe_sigmoid(R1.y1   * g + S[9]  * inv);
            out[i1 * 5 + 3] = safe_sigmoid(R1.x2   * g + S[10] * inv);
            out[i1 * 5 + 4] = safe_sigmoid(R1.y2   * g + S[11] * inv);
        }
    }
}

extern "C" void kernel_launch(void* const* d_in, const int* in_sizes, int n_in,
                              void* d_out, int out_size) {
    // x = the big tensor, gamma = the 1-element one (ordering-proof).
    int xi = 0, gi = (n_in > 1) ? 1 : 0;
    if (n_in > 1 && in_sizes[1] > in_sizes[0]) { xi = 1; gi = 0; }

    const float* x     = (const float*)d_in[xi];
    const float* gamma = (const float*)d_in[gi];
    float* out         = (float*)d_out;

    // Bytes-vs-elements detection via the 1-element gamma.
    const int denom = (n_in > 1 && in_sizes[gi] == 4) ? 20 : 5;
    int n = in_sizes[xi] / denom;
    if (out_size > 0) {
        int n_out = out_size / denom;
        if (n_out > 0 && n_out < n) n = n_out;
    }
    if (n > NMAX) n = NMAX;
    if (n <= 0) n = 1;

    tgam_prep<<<(n + 127) / 128, 128>>>(x, n);
    tgam_attn2<<<(n + 1) / 2, 256>>>(gamma, out, n);
}